// round 11
// baseline (speedup 1.0000x reference)
#include <cuda_runtime.h>
#include <cstdint>

// Problem constants
#define NTOT 8192            // B*N patch tiles
#define NGROUP (NTOT / 8)    // 1024
#define GRID (NGROUP * 9)    // 9216: 8 matvec CTAs + 1 epilogue CTA per group
#define INV_TEMP 10.0f
#define LN_EPS 1e-5f

__device__ float g_raw[NTOT * 64];          // raw matvec results
__device__ unsigned int g_flag[NTOT];       // per-patch ready flags (0-init, restored to 0)

__global__ __launch_bounds__(256)
void scs_fused(const float* __restrict__ spikes,
               const float* __restrict__ Wd,
               const float* __restrict__ gamma,
               const float* __restrict__ beta,
               const float* __restrict__ gates,
               const float* __restrict__ biases,
               float* __restrict__ out) {
    const int blk   = blockIdx.x;
    const int group = blk / 9;
    const int role  = blk - group * 9;
    const int tid   = threadIdx.x;

    if (role < 8) {
        // ================= PRODUCER: streaming matvec for one patch =================
        const int g  = (group << 3) + role;
        const int b  = g >> 10;
        const int n  = g & 1023;
        const int py = n >> 5;
        const int px = n & 31;

        // per-warp direct patch load: lane (tid&15) gets patch float4 jp
        const int jp = tid & 15;
        const float4* sp = (const float4*)(spikes + ((size_t)b << 16)
                                           + ((py << 3) + (jp >> 1)) * 256
                                           + (px << 3) + ((jp & 1) << 2));
        const float4 p = __ldg(sp);

        // warp-contiguous streaming W loads (512B per warp instruction)
        const float4* Wp = (const float4*)(Wd + ((size_t)g << 12));
        const float4 w0 = __ldcs(Wp + tid);
        const float4 w1 = __ldcs(Wp + tid + 256);
        const float4 w2 = __ldcs(Wp + tid + 512);
        const float4 w3 = __ldcs(Wp + tid + 768);

        float a0 = w0.x * p.x + w0.y * p.y + w0.z * p.z + w0.w * p.w;
        float a1 = w1.x * p.x + w1.y * p.y + w1.z * p.z + w1.w * p.w;
        float a2 = w2.x * p.x + w2.y * p.y + w2.z * p.z + w2.w * p.w;
        float a3 = w3.x * p.x + w3.y * p.y + w3.z * p.z + w3.w * p.w;
#pragma unroll
        for (int o = 1; o < 16; o <<= 1) {
            a0 += __shfl_xor_sync(0xffffffffu, a0, o);
            a1 += __shfl_xor_sync(0xffffffffu, a1, o);
            a2 += __shfl_xor_sync(0xffffffffu, a2, o);
            a3 += __shfl_xor_sync(0xffffffffu, a3, o);
        }
        if (jp == 0) {
            const int r0 = tid >> 4;
            float* dst = g_raw + ((size_t)g << 6);
            dst[r0]      = a0;
            dst[r0 + 16] = a1;
            dst[r0 + 32] = a2;
            dst[r0 + 48] = a3;
        }
        __syncthreads();                       // all warps' raw stores issued
        if (tid == 0) {
            __threadfence();                   // raw visible device-wide
            atomicExch(&g_flag[g], 1u);        // publish
        }
    } else {
        // ================= CONSUMER: LN + softmax + affine + fold (1 warp/patch) ====
        const int w  = tid >> 5;
        const int l  = tid & 31;
        const int l2 = l + 32;
        const int g  = (group << 3) + w;
        const int b  = g >> 10;
        const int n  = g & 1023;
        const int py = n >> 5;
        const int px = n & 31;

        // pre-dependency work (independent of producer)
        const float gm0 = __ldg(&gamma[l]),  gm1 = __ldg(&gamma[l2]);
        const float bt0 = __ldg(&beta[l]),   bt1 = __ldg(&beta[l2]);
        const float gt  = __ldg(&gates[n]);
        const float bi  = __ldg(&biases[n]);

        const float* sb = spikes + ((size_t)b << 16) + (py << 3) * 256 + (px << 3);
        const float q0 = __ldg(&sb[(l  >> 3) * 256 + (l  & 7)]);
        const float q1 = __ldg(&sb[(l2 >> 3) * 256 + (l2 & 7)]);
        float ps = q0 + q1;
#pragma unroll
        for (int o = 16; o > 0; o >>= 1)
            ps += __shfl_xor_sync(0xffffffffu, ps, o);
        const float affine = gt * ps + bi;

        // wait for this patch's producer
        if (l == 0) {
            while (atomicCAS(&g_flag[g], 1u, 1u) == 0u) { }
        }
        __syncwarp();
        __threadfence();                       // acquire

        const float* raw = g_raw + ((size_t)g << 6);
        const float v0 = __ldcg(&raw[l]);      // L2 path (no stale L1)
        const float v1 = __ldcg(&raw[l2]);
        __syncwarp();                          // all lanes have read raw
        if (l == 0) g_flag[g] = 0u;            // restore 0 for next graph replay

        float sm = v0 + v1;
        float s2 = v0 * v0 + v1 * v1;
#pragma unroll
        for (int o = 16; o > 0; o >>= 1) {
            sm += __shfl_xor_sync(0xffffffffu, sm, o);
            s2 += __shfl_xor_sync(0xffffffffu, s2, o);
        }
        const float mu   = sm * (1.0f / 64.0f);
        const float rstd = rsqrtf(s2 * (1.0f / 64.0f) - mu * mu + LN_EPS);

        const float z0 = ((v0 - mu) * rstd * gm0 + bt0) * INV_TEMP;
        const float z1 = ((v1 - mu) * rstd * gm1 + bt1) * INV_TEMP;

        float mx = fmaxf(z0, z1);
#pragma unroll
        for (int o = 16; o > 0; o >>= 1)
            mx = fmaxf(mx, __shfl_xor_sync(0xffffffffu, mx, o));

        const float e0 = __expf(z0 - mx);
        const float e1 = __expf(z1 - mx);
        float se = e0 + e1;
#pragma unroll
        for (int o = 16; o > 0; o >>= 1)
            se += __shfl_xor_sync(0xffffffffu, se, o);

        const float scale = affine / se;

        float* ob = out + ((size_t)b << 16) + (py << 3) * 256 + (px << 3);
        ob[(l  >> 3) * 256 + (l  & 7)] = e0 * scale;
        ob[(l2 >> 3) * 256 + (l2 & 7)] = e1 * scale;
    }
}

extern "C" void kernel_launch(void* const* d_in, const int* in_sizes, int n_in,
                              void* d_out, int out_size) {
    const float* spikes = (const float*)d_in[0];
    const float* Wd     = (const float*)d_in[1];
    const float* gamma  = (const float*)d_in[2];
    const float* beta   = (const float*)d_in[3];
    const float* gates  = (const float*)d_in[4];
    const float* biases = (const float*)d_in[5];
    float* out = (float*)d_out;

    scs_fused<<<GRID, 256>>>(spikes, Wd, gamma, beta, gates, biases, out);
}

// round 12
// speedup vs baseline: 1.3061x; 1.3061x over previous
#include <cuda_runtime.h>
#include <cstdint>

// Problem constants
#define NTOT 8192            // B*N patch tiles
#define INV_TEMP 10.0f
#define LN_EPS 1e-5f

// One WARP handles one whole patch: matvec + LN + softmax + affine + store.
// No shared memory, no __syncthreads, no inter-CTA coupling.
__global__ __launch_bounds__(128, 8)
void scs_warp(const float* __restrict__ spikes,
              const float* __restrict__ Wd,
              const float* __restrict__ gamma,
              const float* __restrict__ beta,
              const float* __restrict__ gates,
              const float* __restrict__ biases,
              float* __restrict__ out) {
    const int l   = threadIdx.x & 31;
    const int wid = threadIdx.x >> 5;
    const int g   = (blockIdx.x << 2) + wid;      // patch tile
    const int b   = g >> 10;
    const int n   = g & 1023;
    const int py  = n >> 5;
    const int px  = n & 31;

    // ---- patch float4: lane l takes part jq = l&15 (two halves duplicate) ----
    const int jq = l & 15;
    const float4 p = __ldg((const float4*)(spikes + ((size_t)b << 16)
                                           + ((py << 3) + (jq >> 1)) * 256
                                           + (px << 3) + ((jq & 1) << 2)));

    // patch spike mass: reduce over the 16 parts (bits 0..3)
    float ps = p.x + p.y + p.z + p.w;
    ps += __shfl_xor_sync(0xffffffffu, ps, 1);
    ps += __shfl_xor_sync(0xffffffffu, ps, 2);
    ps += __shfl_xor_sync(0xffffffffu, ps, 4);
    ps += __shfl_xor_sync(0xffffffffu, ps, 8);

    const bool b2 = (l >> 2) & 1;
    const bool b3 = (l >> 3) & 1;
    const int  d  = ((l >> 2) & 1) * 4 + ((l >> 3) & 1) * 2 + (l >> 4);  // 0..7

    // ---- matvec: 8 chunks; each ends with ONE fully-reduced row per lane ----
    // f = l + 32k, k = 4c+j  ->  row(f) = 8c + 2j + (l>>4), part(f) = l&15
    const float4* Wp = (const float4*)(Wd + ((size_t)g << 12));
    float R[8];
#pragma unroll
    for (int c = 0; c < 8; ++c) {
        const float4 w0 = __ldcs(Wp + l + 128 * c);
        const float4 w1 = __ldcs(Wp + l + 128 * c + 32);
        const float4 w2 = __ldcs(Wp + l + 128 * c + 64);
        const float4 w3 = __ldcs(Wp + l + 128 * c + 96);

        const float a0 = w0.x * p.x + w0.y * p.y + w0.z * p.z + w0.w * p.w; // row 8c+0+h
        const float a1 = w1.x * p.x + w1.y * p.y + w1.z * p.z + w1.w * p.w; // row 8c+2+h
        const float a2 = w2.x * p.x + w2.y * p.y + w2.z * p.z + w2.w * p.w; // row 8c+4+h
        const float a3 = w3.x * p.x + w3.y * p.y + w3.z * p.z + w3.w * p.w; // row 8c+6+h

        // distribute-reduce over the 16 parts:
        // step A (o=8): keep row (2*b3), receive partner's same row
        const float tA = b3 ? a0 : a1, rA = b3 ? a1 : a0;
        const float u0 = rA + __shfl_xor_sync(0xffffffffu, tA, 8);   // row 8c+2*b3+h
        const float tB = b3 ? a2 : a3, rB = b3 ? a3 : a2;
        const float u1 = rB + __shfl_xor_sync(0xffffffffu, tB, 8);   // row 8c+4+2*b3+h
        // step B (o=4)
        const float tC = b2 ? u0 : u1, rC = b2 ? u1 : u0;
        float v = rC + __shfl_xor_sync(0xffffffffu, tC, 4);          // row 8c+4*b2+2*b3+h
        // steps C,D: plain reduce over bits 1,0
        v += __shfl_xor_sync(0xffffffffu, v, 2);
        v += __shfl_xor_sync(0xffffffffu, v, 1);
        R[c] = v;                                                    // row 8c+d, full sum
    }

    // ---- LayerNorm stats: local tree + 3 shuffles (o=4,8,16 span bits 2,3,4) ----
    float sm = ((R[0] + R[1]) + (R[2] + R[3])) + ((R[4] + R[5]) + (R[6] + R[7]));
    float s2 = R[0]*R[0] + R[1]*R[1] + R[2]*R[2] + R[3]*R[3]
             + R[4]*R[4] + R[5]*R[5] + R[6]*R[6] + R[7]*R[7];
    sm += __shfl_xor_sync(0xffffffffu, sm, 4);
    s2 += __shfl_xor_sync(0xffffffffu, s2, 4);
    sm += __shfl_xor_sync(0xffffffffu, sm, 8);
    s2 += __shfl_xor_sync(0xffffffffu, s2, 8);
    sm += __shfl_xor_sync(0xffffffffu, sm, 16);
    s2 += __shfl_xor_sync(0xffffffffu, s2, 16);

    const float mu   = sm * (1.0f / 64.0f);
    const float rstd = rsqrtf(s2 * (1.0f / 64.0f) - mu * mu + LN_EPS);

    // ---- z values (in place): row 8c+d uses gamma/beta[8c+d] (L1-hot) ----
#pragma unroll
    for (int c = 0; c < 8; ++c) {
        const float gm = __ldg(&gamma[8 * c + d]);
        const float bt = __ldg(&beta[8 * c + d]);
        R[c] = ((R[c] - mu) * rstd * gm + bt) * INV_TEMP;
    }

    // ---- softmax: max ----
    float mx = fmaxf(fmaxf(fmaxf(R[0], R[1]), fmaxf(R[2], R[3])),
                     fmaxf(fmaxf(R[4], R[5]), fmaxf(R[6], R[7])));
    mx = fmaxf(mx, __shfl_xor_sync(0xffffffffu, mx, 4));
    mx = fmaxf(mx, __shfl_xor_sync(0xffffffffu, mx, 8));
    mx = fmaxf(mx, __shfl_xor_sync(0xffffffffu, mx, 16));

#pragma unroll
    for (int c = 0; c < 8; ++c)
        R[c] = __expf(R[c] - mx);

    float se = ((R[0] + R[1]) + (R[2] + R[3])) + ((R[4] + R[5]) + (R[6] + R[7]));
    se += __shfl_xor_sync(0xffffffffu, se, 4);
    se += __shfl_xor_sync(0xffffffffu, se, 8);
    se += __shfl_xor_sync(0xffffffffu, se, 16);

    const float scale = (__ldg(&gates[n]) * ps + __ldg(&biases[n])) / se;

    // ---- store: lane writes rows c0 = l&3 and c0+4 (pixel (c, d) of 8x8 patch) ----
    const int c0 = l & 3;
    float e_lo = R[0], e_hi = R[4];
#pragma unroll
    for (int c = 1; c < 4; ++c) {
        if (c0 == c) { e_lo = R[c]; e_hi = R[c + 4]; }
    }
    float* ob = out + ((size_t)b << 16) + (py << 3) * 256 + (px << 3) + d;
    ob[c0 * 256]       = e_lo * scale;
    ob[(c0 + 4) * 256] = e_hi * scale;
}

extern "C" void kernel_launch(void* const* d_in, const int* in_sizes, int n_in,
                              void* d_out, int out_size) {
    const float* spikes = (const float*)d_in[0];
    const float* Wd     = (const float*)d_in[1];
    const float* gamma  = (const float*)d_in[2];
    const float* beta   = (const float*)d_in[3];
    const float* gates  = (const float*)d_in[4];
    const float* biases = (const float*)d_in[5];
    float* out = (float*)d_out;

    scs_warp<<<NTOT / 4, 128>>>(spikes, Wd, gamma, beta, gates, biases, out);
}